// round 9
// baseline (speedup 1.0000x reference)
#include <cuda_runtime.h>
#include <cuda_bf16.h>
#include <cuda_fp16.h>
#include <cstddef>
#include <cstdint>

// Problem constants: N=50000, F=128, H=8, HID=8, CLS=40, E=1.6M
#define NMAX 50000
#define EMAX 1700000

// ---------------- static device scratch ----------------
// hs row = 48 floats (192B): [0..31] = half[64] features, [32..39] s_src, [40..47] s_dst
__device__ float g_hs   [(size_t)NMAX * 48];
__device__ float g_act  [(size_t)NMAX * 64];          // layer-4 activation fp32 (score GEMM input)
__device__ __half g_acth[(size_t)NMAX * 64];          // layer-4 activation fp16 (gather)
__device__ __nv_bfloat16 g_xh[(size_t)NMAX * 128];
__device__ __nv_bfloat16 g_xl[(size_t)NMAX * 128];
__device__ __nv_bfloat16 g_ah[(size_t)NMAX * 64];
__device__ __nv_bfloat16 g_al[(size_t)NMAX * 64];
__device__ float g_sbuf [(size_t)NMAX * 16];
__device__ int   g_col  [EMAX];
__device__ int   g_rowptr[NMAX + 1];
__device__ int   g_cursor[NMAX];
__device__ int   g_cnt   [NMAX];
__device__ int   g_bsum [64];
__device__ __nv_bfloat16 g_yh[(size_t)NMAX * 512];
__device__ __nv_bfloat16 g_yl[(size_t)NMAX * 512];
__device__ __nv_bfloat16 g_Wth[40 * 512];
__device__ __nv_bfloat16 g_Wtl[40 * 512];
__device__ __nv_bfloat16 g_Bth[4 * 80 * 128];         // per-layer stride 10240
__device__ __nv_bfloat16 g_Btl[4 * 80 * 128];
__device__ float g_Wfold[64 * 16];

// ---------------- CSR build ----------------
__global__ void k_hist(const int* __restrict__ dst, int* cnt, int E) {
    int i = blockIdx.x * blockDim.x + threadIdx.x;
    if (i < E) atomicAdd(&cnt[dst[i]], 1);
}

__global__ void k_scan1(const int* __restrict__ cnt, int* rowptr, int* bsum, int n) {
    __shared__ int sm[1024];
    int tid = threadIdx.x;
    int i = blockIdx.x * 1024 + tid;
    int v = (i < n) ? cnt[i] + 1 : 0;          // +1 = self loop
    sm[tid] = v;
    __syncthreads();
    for (int off = 1; off < 1024; off <<= 1) {
        int t = (tid >= off) ? sm[tid - off] : 0;
        __syncthreads();
        sm[tid] += t;
        __syncthreads();
    }
    if (i < n) rowptr[i] = sm[tid] - v;
    if (tid == 1023) bsum[blockIdx.x] = sm[1023];
}

__global__ void k_scan2(int* bsum, int nb) {
    __shared__ int sm[64];
    int tid = threadIdx.x;
    sm[tid] = (tid < nb) ? bsum[tid] : 0;
    __syncthreads();
    if (tid == 0) {
        int run = 0;
        for (int j = 0; j < nb; j++) { int t = sm[j]; sm[j] = run; run += t; }
    }
    __syncthreads();
    if (tid < nb) bsum[tid] = sm[tid];
}

__global__ void k_scan3(int* rowptr, int* cursor, const int* __restrict__ bsum,
                        const int* __restrict__ cnt, int n) {
    int i = blockIdx.x * blockDim.x + threadIdx.x;
    if (i < n) {
        int v = rowptr[i] + bsum[i >> 10];
        rowptr[i] = v;
        cursor[i] = v;
        if (i == n - 1) rowptr[n] = v + cnt[i] + 1;
    }
}

__global__ void k_scatter(const int* __restrict__ ei, int* cursor, int* col, int E, int n) {
    int i = blockIdx.x * blockDim.x + threadIdx.x;
    if (i < E) {
        int s = ei[i];
        int d = ei[E + i];
        int p = atomicAdd(&cursor[d], 1);
        col[p] = s;
    } else if (i < E + n) {
        int nd = i - E;
        int p = atomicAdd(&cursor[nd], 1);
        col[p] = nd;
    }
}

// ---------------- split fp32 -> bf16 hi/lo planes ----------------
__global__ void k_split(const float* __restrict__ A, __nv_bfloat16* __restrict__ Ah,
                        __nv_bfloat16* __restrict__ Al, int sz)
{
    int i = blockIdx.x * blockDim.x + threadIdx.x;
    if (i < sz) {
        float v = A[i];
        __nv_bfloat16 hi = __float2bfloat16_rn(v);
        Ah[i] = hi;
        Al[i] = __float2bfloat16_rn(v - __bfloat162float(hi));
    }
}

// ---------------- fused weight prep: all layers in one kernel ----------------
// [0,10240): L0 BcatT K=128 | [10240,25600): L1-3 K=64 | [25600,26624): layer-5 fold
// [26624,47104): W5 transposed split planes
__global__ void k_prep(
    const float* __restrict__ W1, const float* __restrict__ as1, const float* __restrict__ ad1,
    const float* __restrict__ W2, const float* __restrict__ as2, const float* __restrict__ ad2,
    const float* __restrict__ W3, const float* __restrict__ as3, const float* __restrict__ ad3,
    const float* __restrict__ W4, const float* __restrict__ as4, const float* __restrict__ ad4,
    const float* __restrict__ W5, const float* __restrict__ as5, const float* __restrict__ ad5,
    __nv_bfloat16* __restrict__ Bth, __nv_bfloat16* __restrict__ Btl,
    float* __restrict__ Wfold,
    __nv_bfloat16* __restrict__ Wth, __nv_bfloat16* __restrict__ Wtl)
{
    int idx = blockIdx.x * blockDim.x + threadIdx.x;
    if (idx >= 47104) return;
    const float* Ws[4] = {W1, W2, W3, W4};
    const float* av[4] = {as1, as2, as3, as4};
    const float* dv[4] = {ad1, ad2, ad3, ad4};

    if (idx < 25600) {                         // BcatT segments
        int L, K, t;
        if (idx < 10240) { L = 0; K = 128; t = idx; }
        else { int r = idx - 10240; L = 1 + r / 5120; K = 64; t = r % 5120; }
        int c = t / K;
        int k = t % K;
        const float* W = Ws[L];
        float val;
        if (c < 64) {
            val = W[(size_t)k * 64 + c];
        } else {
            int j = c - 64;
            int h = j & 7;
            const float* a = (j < 8) ? av[L] : dv[L];
            float sum = 0.f;
#pragma unroll
            for (int q = 0; q < 8; q++)
                sum += W[(size_t)k * 64 + h * 8 + q] * a[h * 8 + q];
            val = sum;
        }
        __nv_bfloat16 hi = __float2bfloat16_rn(val);
        Bth[L * 10240 + c * K + k] = hi;
        Btl[L * 10240 + c * K + k] = __float2bfloat16_rn(val - __bfloat162float(hi));
    } else if (idx < 26624) {                  // layer-5 score fold: Wfold[64][16]
        int t = idx - 25600;
        int k = t >> 4;
        int j = t & 15;
        int h = j & 7;
        const float* a = (j < 8) ? as5 : ad5;
        float sum = 0.f;
        for (int c = 0; c < 40; c++)
            sum += W5[(size_t)k * 320 + h * 40 + c] * a[h * 40 + c];
        Wfold[t] = sum;
    } else {                                   // W5 transposed block-diag planes
        int t = idx - 26624;
        int c  = t / 512;
        int kk = t % 512;
        int h  = kk >> 6;
        int k  = kk & 63;
        float w = W5[(size_t)k * 320 + h * 40 + c];
        __nv_bfloat16 hi = __float2bfloat16_rn(w);
        Wth[t] = hi;
        Wtl[t] = __float2bfloat16_rn(w - __bfloat162float(hi));
    }
}

// ---------------- small fp32 SGEMM (layer-5 scores) ----------------
template<int TN>
__global__ __launch_bounds__(256) void k_gemm(
    const float* __restrict__ A, const float* __restrict__ B, float* __restrict__ C,
    int M, int Nc, int K)
{
    const int BN = 16 * TN;
    __shared__ float As[16][132];
    __shared__ float Bs[16][BN];
    int tid = threadIdx.x;
    int bm = blockIdx.y * 128;
    int bn = blockIdx.x * BN;
    int tx = tid & 15;
    int ty = tid >> 4;
    float acc[8][TN];
#pragma unroll
    for (int i = 0; i < 8; i++)
#pragma unroll
        for (int j = 0; j < TN; j++) acc[i][j] = 0.f;

    for (int k0 = 0; k0 < K; k0 += 16) {
#pragma unroll
        for (int it = 0; it < 2; it++) {
            int idx = tid + it * 256;
            int m  = idx >> 2;
            int kq = (idx & 3) * 4;
            int gm = bm + m;
            float4 v = make_float4(0.f, 0.f, 0.f, 0.f);
            if (gm < M) v = *(const float4*)(A + (size_t)gm * K + k0 + kq);
            As[kq + 0][m] = v.x;
            As[kq + 1][m] = v.y;
            As[kq + 2][m] = v.z;
            As[kq + 3][m] = v.w;
        }
        for (int idx = tid; idx < 16 * BN; idx += 256) {
            int kk = idx / BN;
            int cc = idx % BN;
            int gc = bn + cc;
            float v = 0.f;
            if (gc < Nc) v = B[(size_t)(k0 + kk) * Nc + gc];
            Bs[kk][cc] = v;
        }
        __syncthreads();
#pragma unroll
        for (int kk = 0; kk < 16; kk++) {
            float4 a0 = *(const float4*)(&As[kk][ty * 8]);
            float4 a1 = *(const float4*)(&As[kk][ty * 8 + 4]);
            float av[8] = {a0.x, a0.y, a0.z, a0.w, a1.x, a1.y, a1.z, a1.w};
            float bv[TN];
#pragma unroll
            for (int j = 0; j < TN; j++) bv[j] = Bs[kk][tx * TN + j];
#pragma unroll
            for (int i = 0; i < 8; i++)
#pragma unroll
                for (int j = 0; j < TN; j++) acc[i][j] += av[i] * bv[j];
        }
        __syncthreads();
    }
#pragma unroll
    for (int i = 0; i < 8; i++) {
        int gm = bm + ty * 8 + i;
        if (gm >= M) continue;
#pragma unroll
        for (int j = 0; j < TN; j++) {
            int gc = bn + tx * TN + j;
            if (gc < Nc) C[(size_t)gm * Nc + gc] = acc[i][j];
        }
    }
}

// ---------------- layers 1-4 fused GEMM on tensor cores -> hs (half feats) ----
__global__ __launch_bounds__(128) void k_gemm80_tc(
    const __nv_bfloat16* __restrict__ Ah, const __nv_bfloat16* __restrict__ Al,
    const __nv_bfloat16* __restrict__ Bth, const __nv_bfloat16* __restrict__ Btl,
    float* __restrict__ C, int n, int K)
{
    __shared__ __nv_bfloat16 sAh[64 * 72];
    __shared__ __nv_bfloat16 sAl[64 * 72];
    __shared__ __nv_bfloat16 sBh[80 * 72];
    __shared__ __nv_bfloat16 sBl[80 * 72];

    int tid  = threadIdx.x;
    int bm   = blockIdx.x * 64;
    int wid  = tid >> 5;
    int lane = tid & 31;
    int g    = lane >> 2;
    int t2   = (lane & 3) * 2;
    int mw   = wid * 16;
    int Ku   = K >> 1;

    float c0[10], c1[10], c2[10], c3[10];
#pragma unroll
    for (int j = 0; j < 10; j++) { c0[j] = c1[j] = c2[j] = c3[j] = 0.f; }

    const uint32_t* ah32 = (const uint32_t*)Ah;
    const uint32_t* al32 = (const uint32_t*)Al;
    const uint32_t* bh32 = (const uint32_t*)Bth;
    const uint32_t* bl32 = (const uint32_t*)Btl;

    for (int k0 = 0; k0 < K; k0 += 64) {
#pragma unroll
        for (int i = 0; i < 16; i++) {
            int idx = tid + i * 128;
            int row = idx >> 5;
            int cu  = idx & 31;
            int gr  = bm + row;
            uint32_t vh = 0, vl = 0;
            if (gr < n) {
                size_t off = (size_t)gr * Ku + (k0 >> 1) + cu;
                vh = ah32[off];
                vl = al32[off];
            }
            *(uint32_t*)(&sAh[row * 72 + cu * 2]) = vh;
            *(uint32_t*)(&sAl[row * 72 + cu * 2]) = vl;
        }
#pragma unroll
        for (int i = 0; i < 20; i++) {
            int idx = tid + i * 128;
            int c  = idx >> 5;
            int cu = idx & 31;
            size_t off = (size_t)c * Ku + (k0 >> 1) + cu;
            *(uint32_t*)(&sBh[c * 72 + cu * 2]) = bh32[off];
            *(uint32_t*)(&sBl[c * 72 + cu * 2]) = bl32[off];
        }
        __syncthreads();

#pragma unroll
        for (int ks = 0; ks < 64; ks += 16) {
            int arow0 = (mw + g) * 72 + ks + t2;
            int arow1 = (mw + g + 8) * 72 + ks + t2;
            uint32_t a0h = *(const uint32_t*)(&sAh[arow0]);
            uint32_t a1h = *(const uint32_t*)(&sAh[arow1]);
            uint32_t a2h = *(const uint32_t*)(&sAh[arow0 + 8]);
            uint32_t a3h = *(const uint32_t*)(&sAh[arow1 + 8]);
            uint32_t a0l = *(const uint32_t*)(&sAl[arow0]);
            uint32_t a1l = *(const uint32_t*)(&sAl[arow1]);
            uint32_t a2l = *(const uint32_t*)(&sAl[arow0 + 8]);
            uint32_t a3l = *(const uint32_t*)(&sAl[arow1 + 8]);
#pragma unroll
            for (int j = 0; j < 10; j++) {
                int brow = (j * 8 + g) * 72 + ks + t2;
                uint32_t b0h = *(const uint32_t*)(&sBh[brow]);
                uint32_t b1h = *(const uint32_t*)(&sBh[brow + 8]);
                uint32_t b0l = *(const uint32_t*)(&sBl[brow]);
                uint32_t b1l = *(const uint32_t*)(&sBl[brow + 8]);
                asm volatile(
                    "mma.sync.aligned.m16n8k16.row.col.f32.bf16.bf16.f32 "
                    "{%0,%1,%2,%3}, {%4,%5,%6,%7}, {%8,%9}, {%0,%1,%2,%3};"
                    : "+f"(c0[j]), "+f"(c1[j]), "+f"(c2[j]), "+f"(c3[j])
                    : "r"(a0h), "r"(a1h), "r"(a2h), "r"(a3h), "r"(b0h), "r"(b1h));
                asm volatile(
                    "mma.sync.aligned.m16n8k16.row.col.f32.bf16.bf16.f32 "
                    "{%0,%1,%2,%3}, {%4,%5,%6,%7}, {%8,%9}, {%0,%1,%2,%3};"
                    : "+f"(c0[j]), "+f"(c1[j]), "+f"(c2[j]), "+f"(c3[j])
                    : "r"(a0h), "r"(a1h), "r"(a2h), "r"(a3h), "r"(b0l), "r"(b1l));
                asm volatile(
                    "mma.sync.aligned.m16n8k16.row.col.f32.bf16.bf16.f32 "
                    "{%0,%1,%2,%3}, {%4,%5,%6,%7}, {%8,%9}, {%0,%1,%2,%3};"
                    : "+f"(c0[j]), "+f"(c1[j]), "+f"(c2[j]), "+f"(c3[j])
                    : "r"(a0l), "r"(a1l), "r"(a2l), "r"(a3l), "r"(b0h), "r"(b1h));
            }
        }
        __syncthreads();
    }

    int row0 = bm + mw + g;
    int row1 = row0 + 8;
#pragma unroll
    for (int j = 0; j < 10; j++) {
        if (j < 8) {                            // features -> half2
            if (row0 < n)
                *(__half2*)((__half*)(C + (size_t)row0 * 48) + j * 8 + t2) =
                    __float22half2_rn(make_float2(c0[j], c1[j]));
            if (row1 < n)
                *(__half2*)((__half*)(C + (size_t)row1 * 48) + j * 8 + t2) =
                    __float22half2_rn(make_float2(c2[j], c3[j]));
        } else {                                // scores -> fp32
            int fo = 32 + (j - 8) * 8 + t2;
            if (row0 < n)
                *(float2*)(C + (size_t)row0 * 48 + fo) = make_float2(c0[j], c1[j]);
            if (row1 < n)
                *(float2*)(C + (size_t)row1 * 48 + fo) = make_float2(c2[j], c3[j]);
        }
    }
}

// ---------------- concat-layer aggregation: fp16 feature gather ---------------
__global__ __launch_bounds__(256) void k_agg_cat(
    const float* __restrict__ hs, const int* __restrict__ rowptr,
    const int* __restrict__ colx, const float* __restrict__ bias,
    __nv_bfloat16* __restrict__ oh, __nv_bfloat16* __restrict__ ol,
    __half* __restrict__ outh, float* __restrict__ outf, int n)
{
    int node = (blockIdx.x * blockDim.x + threadIdx.x) >> 5;
    if (node >= n) return;
    int lane = threadIdx.x & 31;
    int beg = rowptr[node], end = rowptr[node + 1];

    int sub = lane >> 4;
    int r   = lane & 15;
    int h   = r >> 1;
    int q   = r & 1;
    float sdv = __ldg(hs + (size_t)node * 48 + 40 + h);
    int hoff = h * 8 + q * 4;                  // half offset of this lane's 4 channels

    float4 acc = make_float4(0.f, 0.f, 0.f, 0.f);
    float d = 0.f;

    int e0 = beg;
    for (; e0 + 4 <= end; e0 += 4) {
        int siA = __ldg(colx + e0 + sub);
        int siB = __ldg(colx + e0 + 2 + sub);
        const float* rA = hs + (size_t)siA * 48;
        const float* rB = hs + (size_t)siB * 48;
        float sA = __ldg(rA + 32 + h);
        float sB = __ldg(rB + 32 + h);
        uint2 uA = __ldg((const uint2*)((const __half*)rA + hoff));
        uint2 uB = __ldg((const uint2*)((const __half*)rB + hoff));
        float2 fA0 = __half22float2(*(const __half2*)&uA.x);
        float2 fA1 = __half22float2(*(const __half2*)&uA.y);
        float2 fB0 = __half22float2(*(const __half2*)&uB.x);
        float2 fB1 = __half22float2(*(const __half2*)&uB.y);
        float aA = sA + sdv; aA = aA > 0.f ? aA : 0.2f * aA;
        float aB = sB + sdv; aB = aB > 0.f ? aB : 0.2f * aB;
        float eA = __expf(aA);
        float eB = __expf(aB);
        if (q == 0) d += eA + eB;
        acc.x += eA * fA0.x + eB * fB0.x;
        acc.y += eA * fA0.y + eB * fB0.y;
        acc.z += eA * fA1.x + eB * fB1.x;
        acc.w += eA * fA1.y + eB * fB1.y;
    }
    for (; e0 < end; e0 += 2) {
        int ee = e0 + sub;
        bool ok = ee < end;
        int si = ok ? __ldg(colx + ee) : node;
        const float* row = hs + (size_t)si * 48;
        float ssv = __ldg(row + 32 + h);
        uint2 u = __ldg((const uint2*)((const __half*)row + hoff));
        float2 f0 = __half22float2(*(const __half2*)&u.x);
        float2 f1 = __half22float2(*(const __half2*)&u.y);
        float al = ssv + sdv; al = al > 0.f ? al : 0.2f * al;
        float ex = ok ? __expf(al) : 0.f;
        if (q == 0) d += ex;
        acc.x += ex * f0.x;
        acc.y += ex * f0.y;
        acc.z += ex * f1.x;
        acc.w += ex * f1.y;
    }

    acc.x += __shfl_xor_sync(0xffffffffu, acc.x, 16);
    acc.y += __shfl_xor_sync(0xffffffffu, acc.y, 16);
    acc.z += __shfl_xor_sync(0xffffffffu, acc.z, 16);
    acc.w += __shfl_xor_sync(0xffffffffu, acc.w, 16);
    d     += __shfl_xor_sync(0xffffffffu, d, 16);
    d     += __shfl_xor_sync(0xffffffffu, d, 1);

    if (sub == 0) {
        float inv = 1.f / (d + 1e-16f);
        int ch = hoff;
        float4 b = __ldg((const float4*)(bias + ch));
        float4 rv;
        rv.x = acc.x * inv + b.x;
        rv.y = acc.y * inv + b.y;
        rv.z = acc.z * inv + b.z;
        rv.w = acc.w * inv + b.w;
        rv.x = rv.x > 0.f ? rv.x : 0.2f * rv.x;
        rv.y = rv.y > 0.f ? rv.y : 0.2f * rv.y;
        rv.z = rv.z > 0.f ? rv.z : 0.2f * rv.z;
        rv.w = rv.w > 0.f ? rv.w : 0.2f * rv.w;
        size_t o = (size_t)node * 64 + ch;
        if (oh) {                               // layers 1-3: bf16 planes for next GEMM
            __nv_bfloat16 h0 = __float2bfloat16_rn(rv.x);
            __nv_bfloat16 h1 = __float2bfloat16_rn(rv.y);
            __nv_bfloat16 h2 = __float2bfloat16_rn(rv.z);
            __nv_bfloat16 h3 = __float2bfloat16_rn(rv.w);
            *(__nv_bfloat162*)(oh + o)     = __nv_bfloat162(h0, h1);
            *(__nv_bfloat162*)(oh + o + 2) = __nv_bfloat162(h2, h3);
            __nv_bfloat162 lo01, lo23;
            lo01.x = __float2bfloat16_rn(rv.x - __bfloat162float(h0));
            lo01.y = __float2bfloat16_rn(rv.y - __bfloat162float(h1));
            lo23.x = __float2bfloat16_rn(rv.z - __bfloat162float(h2));
            lo23.y = __float2bfloat16_rn(rv.w - __bfloat162float(h3));
            *(__nv_bfloat162*)(ol + o)     = lo01;
            *(__nv_bfloat162*)(ol + o + 2) = lo23;
        }
        if (outh) {                             // layer 4: half (gather) + fp32 (score GEMM)
            uint2 hp;
            *(__half2*)&hp.x = __float22half2_rn(make_float2(rv.x, rv.y));
            *(__half2*)&hp.y = __float22half2_rn(make_float2(rv.z, rv.w));
            *(uint2*)(outh + o) = hp;
            *(float4*)(outf + o) = rv;
        }
    }
}

// ---------------- layer-5 aggregation: ONE PASS, fp16 x gather ---------------
// lanes r<8 of each edge slot compute head exps; shfl-broadcast to feature lanes.
__global__ __launch_bounds__(256) void k_agg_mean(
    const __half* __restrict__ xh, const float* __restrict__ s,
    const int* __restrict__ rowptr, const int* __restrict__ colx,
    __nv_bfloat16* __restrict__ yh, __nv_bfloat16* __restrict__ yl, int n)
{
    int node = (blockIdx.x * blockDim.x + threadIdx.x) >> 5;
    if (node >= n) return;
    int lane = threadIdx.x & 31;
    int beg = rowptr[node], end = rowptr[node + 1];

    int sub = lane >> 4;
    int r   = lane & 15;
    float sdv = (r < 8) ? __ldg(s + (size_t)node * 16 + 8 + r) : 0.f;

    float4 acc[8];
#pragma unroll
    for (int h = 0; h < 8; h++) acc[h] = make_float4(0.f, 0.f, 0.f, 0.f);
    float dsum = 0.f;

    for (int e0 = beg; e0 < end; e0 += 2) {
        int ee = e0 + sub;
        bool ok = ee < end;
        int si = ok ? __ldg(colx + ee) : node;
        float exv = 0.f;
        if (r < 8) {
            float sc = __ldg(s + (size_t)si * 16 + r) + sdv;
            sc = sc > 0.f ? sc : 0.2f * sc;
            exv = ok ? __expf(sc) : 0.f;
            dsum += exv;
        }
        float ex[8];
#pragma unroll
        for (int h = 0; h < 8; h++)
            ex[h] = __shfl_sync(0xffffffffu, exv, (sub << 4) + h);
        uint2 u = __ldg((const uint2*)(xh + (size_t)si * 64 + r * 4));
        float2 f0 = __half22float2(*(const __half2*)&u.x);
        float2 f1 = __half22float2(*(const __half2*)&u.y);
#pragma unroll
        for (int h = 0; h < 8; h++) {
            acc[h].x += ex[h] * f0.x;
            acc[h].y += ex[h] * f0.y;
            acc[h].z += ex[h] * f1.x;
            acc[h].w += ex[h] * f1.y;
        }
    }

    dsum += __shfl_xor_sync(0xffffffffu, dsum, 16);
    float invv = (r < 8) ? 1.f / (dsum + 1e-16f) : 0.f;
    float inv[8];
#pragma unroll
    for (int h = 0; h < 8; h++)
        inv[h] = __shfl_sync(0xffffffffu, invv, h);

#pragma unroll
    for (int h = 0; h < 8; h++) {
        acc[h].x += __shfl_xor_sync(0xffffffffu, acc[h].x, 16);
        acc[h].y += __shfl_xor_sync(0xffffffffu, acc[h].y, 16);
        acc[h].z += __shfl_xor_sync(0xffffffffu, acc[h].z, 16);
        acc[h].w += __shfl_xor_sync(0xffffffffu, acc[h].w, 16);
    }

    if (sub == 0) {
        int kb = r * 4;
#pragma unroll
        for (int h = 0; h < 8; h++) {
            float w0 = acc[h].x * inv[h];
            float w1 = acc[h].y * inv[h];
            float w2 = acc[h].z * inv[h];
            float w3 = acc[h].w * inv[h];
            size_t o = (size_t)node * 512 + (size_t)h * 64 + kb;
            __nv_bfloat16 h0 = __float2bfloat16_rn(w0);
            __nv_bfloat16 h1 = __float2bfloat16_rn(w1);
            __nv_bfloat16 h2 = __float2bfloat16_rn(w2);
            __nv_bfloat16 h3 = __float2bfloat16_rn(w3);
            *(__nv_bfloat162*)(yh + o)     = __nv_bfloat162(h0, h1);
            *(__nv_bfloat162*)(yh + o + 2) = __nv_bfloat162(h2, h3);
            __nv_bfloat162 l01, l23;
            l01.x = __float2bfloat16_rn(w0 - __bfloat162float(h0));
            l01.y = __float2bfloat16_rn(w1 - __bfloat162float(h1));
            l23.x = __float2bfloat16_rn(w2 - __bfloat162float(h2));
            l23.y = __float2bfloat16_rn(w3 - __bfloat162float(h3));
            *(__nv_bfloat162*)(yl + o)     = l01;
            *(__nv_bfloat162*)(yl + o + 2) = l23;
        }
    }
}

// ---------------- final tensor-core GEMM + fused lsm ----------------
__global__ __launch_bounds__(128) void k_gemm_tc(
    const __nv_bfloat16* __restrict__ yh, const __nv_bfloat16* __restrict__ yl,
    const __nv_bfloat16* __restrict__ Wth, const __nv_bfloat16* __restrict__ Wtl,
    const float* __restrict__ b5, float* __restrict__ out, int n)
{
    __shared__ __nv_bfloat16 sAh[64 * 72];
    __shared__ __nv_bfloat16 sAl[64 * 72];
    __shared__ __nv_bfloat16 sBh[40 * 72];
    __shared__ __nv_bfloat16 sBl[40 * 72];

    int tid  = threadIdx.x;
    int bm   = blockIdx.x * 64;
    int wid  = tid >> 5;
    int lane = tid & 31;
    int g    = lane >> 2;
    int t2   = (lane & 3) * 2;
    int mw   = wid * 16;

    float c0[5], c1[5], c2[5], c3[5];
#pragma unroll
    for (int j = 0; j < 5; j++) { c0[j] = c1[j] = c2[j] = c3[j] = 0.f; }

    const uint32_t* yh32 = (const uint32_t*)yh;
    const uint32_t* yl32 = (const uint32_t*)yl;
    const uint32_t* wh32 = (const uint32_t*)Wth;
    const uint32_t* wl32 = (const uint32_t*)Wtl;

    for (int k0 = 0; k0 < 512; k0 += 64) {
#pragma unroll
        for (int i = 0; i < 16; i++) {
            int idx = tid + i * 128;
            int row = idx >> 5;
            int cu  = idx & 31;
            int gr  = bm + row;
            uint32_t vh = 0, vl = 0;
            if (gr < n) {
                size_t off = (size_t)gr * 256 + (k0 >> 1) + cu;
                vh = yh32[off];
                vl = yl32[off];
            }
            *(uint32_t*)(&sAh[row * 72 + cu * 2]) = vh;
            *(uint32_t*)(&sAl[row * 72 + cu * 2]) = vl;
        }
#pragma unroll
        for (int i = 0; i < 10; i++) {
            int idx = tid + i * 128;
            int c  = idx >> 5;
            int cu = idx & 31;
            size_t off = (size_t)c * 256 + (k0 >> 1) + cu;
            *(uint32_t*)(&sBh[c * 72 + cu * 2]) = wh32[off];
            *(uint32_t*)(&sBl[c * 72 + cu * 2]) = wl32[off];
        }
        __syncthreads();

#pragma unroll
        for (int ks = 0; ks < 64; ks += 16) {
            int arow0 = (mw + g) * 72 + ks + t2;
            int arow1 = (mw + g + 8) * 72 + ks + t2;
            uint32_t a0h = *(const uint32_t*)(&sAh[arow0]);
            uint32_t a1h = *(const uint32_t*)(&sAh[arow1]);
            uint32_t a2h = *(const uint32_t*)(&sAh[arow0 + 8]);
            uint32_t a3h = *(const uint32_t*)(&sAh[arow1 + 8]);
            uint32_t a0l = *(const uint32_t*)(&sAl[arow0]);
            uint32_t a1l = *(const uint32_t*)(&sAl[arow1]);
            uint32_t a2l = *(const uint32_t*)(&sAl[arow0 + 8]);
            uint32_t a3l = *(const uint32_t*)(&sAl[arow1 + 8]);
#pragma unroll
            for (int j = 0; j < 5; j++) {
                int brow = (j * 8 + g) * 72 + ks + t2;
                uint32_t b0h = *(const uint32_t*)(&sBh[brow]);
                uint32_t b1h = *(const uint32_t*)(&sBh[brow + 8]);
                uint32_t b0l = *(const uint32_t*)(&sBl[brow]);
                uint32_t b1l = *(const uint32_t*)(&sBl[brow + 8]);
                asm volatile(
                    "mma.sync.aligned.m16n8k16.row.col.f32.bf16.bf16.f32 "
                    "{%0,%1,%2,%3}, {%4,%5,%6,%7}, {%8,%9}, {%0,%1,%2,%3};"
                    : "+f"(c0[j]), "+f"(c1[j]), "+f"(c2[j]), "+f"(c3[j])
                    : "r"(a0h), "r"(a1h), "r"(a2h), "r"(a3h), "r"(b0h), "r"(b1h));
                asm volatile(
                    "mma.sync.aligned.m16n8k16.row.col.f32.bf16.bf16.f32 "
                    "{%0,%1,%2,%3}, {%4,%5,%6,%7}, {%8,%9}, {%0,%1,%2,%3};"
                    : "+f"(c0[j]), "+f"(c1[j]), "+f"(c2[j]), "+f"(c3[j])
                    : "r"(a0h), "r"(a1h), "r"(a2h), "r"(a3h), "r"(b0l), "r"(b1l));
                asm volatile(
                    "mma.sync.aligned.m16n8k16.row.col.f32.bf16.bf16.f32 "
                    "{%0,%1,%2,%3}, {%4,%5,%6,%7}, {%8,%9}, {%0,%1,%2,%3};"
                    : "+f"(c0[j]), "+f"(c1[j]), "+f"(c2[j]), "+f"(c3[j])
                    : "r"(a0l), "r"(a1l), "r"(a2l), "r"(a3l), "r"(b0h), "r"(b1h));
            }
        }
        __syncthreads();
    }

    int row0 = bm + mw + g;
    int row1 = row0 + 8;
    float v0[5], w0[5], v1[5], w1[5];
#pragma unroll
    for (int j = 0; j < 5; j++) {
        float2 b = *(const float2*)(b5 + j * 8 + t2);
        v0[j] = c0[j] * 0.125f + b.x;
        w0[j] = c1[j] * 0.125f + b.y;
        v1[j] = c2[j] * 0.125f + b.x;
        w1[j] = c3[j] * 0.125f + b.y;
    }
    float m0 = -1e30f, m1 = -1e30f;
#pragma unroll
    for (int j = 0; j < 5; j++) {
        m0 = fmaxf(m0, fmaxf(v0[j], w0[j]));
        m1 = fmaxf(m1, fmaxf(v1[j], w1[j]));
    }
    m0 = fmaxf(m0, __shfl_xor_sync(0xffffffffu, m0, 1));
    m0 = fmaxf(m0, __shfl_xor_sync(0xffffffffu, m0, 2));
    m1 = fmaxf(m1, __shfl_xor_sync(0xffffffffu, m1, 1));
    m1 = fmaxf(m1, __shfl_xor_sync(0xffffffffu, m1, 2));
    float s0 = 0.f, s1 = 0.f;
#pragma unroll
    for (int j = 0; j < 5; j++) {
        s0 += __expf(v0[j] - m0) + __expf(w0[j] - m0);
        s1 += __expf(v1[j] - m1) + __expf(w1[j] - m1);
    }
    s0 += __shfl_xor_sync(0xffffffffu, s0, 1);
    s0 += __shfl_xor_sync(0xffffffffu, s0, 2);
    s1 += __shfl_xor_sync(0xffffffffu, s1, 1);
    s1 += __shfl_xor_sync(0xffffffffu, s1, 2);
    float lse0 = m0 + __logf(s0);
    float lse1 = m1 + __logf(s1);

    if (row0 < n) {
#pragma unroll
        for (int j = 0; j < 5; j++)
            *(float2*)(out + (size_t)row0 * 40 + j * 8 + t2) =
                make_float2(v0[j] - lse0, w0[j] - lse0);
    }
    if (row1 < n) {
#pragma unroll
        for (int j = 0; j < 5; j++)
            *(float2*)(out + (size_t)row1 * 40 + j * 8 + t2) =
                make_float2(v1[j] - lse1, w1[j] - lse1);
    }
}

// ---------------- host ----------------
static void* sym(const void* s) {
    void* p = nullptr;
    cudaGetSymbolAddress(&p, s);
    return p;
}

extern "C" void kernel_launch(void* const* d_in, const int* in_sizes, int n_in,
                              void* d_out, int out_size)
{
    const float* x   = (const float*)d_in[0];
    const int*   ei  = (const int*)d_in[1];
    const float* Ws[5]  = {(const float*)d_in[2],  (const float*)d_in[6],
                           (const float*)d_in[10], (const float*)d_in[14],
                           (const float*)d_in[18]};
    const float* asv[5] = {(const float*)d_in[3],  (const float*)d_in[7],
                           (const float*)d_in[11], (const float*)d_in[15],
                           (const float*)d_in[19]};
    const float* adv[5] = {(const float*)d_in[4],  (const float*)d_in[8],
                           (const float*)d_in[12], (const float*)d_in[16],
                           (const float*)d_in[20]};
    const float* bs[5]  = {(const float*)d_in[5],  (const float*)d_in[9],
                           (const float*)d_in[13], (const float*)d_in[17],
                           (const float*)d_in[21]};

    int n = in_sizes[0] / 128;
    int E = in_sizes[1] / 2;

    float* hs     = (float*)sym(g_hs);
    float* act    = (float*)sym(g_act);
    __half* acth  = (__half*)sym(g_acth);
    float* sbuf   = (float*)sym(g_sbuf);
    int*   col    = (int*)  sym(g_col);
    int*   rowptr = (int*)  sym(g_rowptr);
    int*   cursor = (int*)  sym(g_cursor);
    int*   cnt    = (int*)  sym(g_cnt);
    int*   bsum   = (int*)  sym(g_bsum);
    __nv_bfloat16* xh  = (__nv_bfloat16*)sym(g_xh);
    __nv_bfloat16* xl  = (__nv_bfloat16*)sym(g_xl);
    __nv_bfloat16* ah  = (__nv_bfloat16*)sym(g_ah);
    __nv_bfloat16* al  = (__nv_bfloat16*)sym(g_al);
    __nv_bfloat16* yh  = (__nv_bfloat16*)sym(g_yh);
    __nv_bfloat16* yl  = (__nv_bfloat16*)sym(g_yl);
    __nv_bfloat16* Wth = (__nv_bfloat16*)sym(g_Wth);
    __nv_bfloat16* Wtl = (__nv_bfloat16*)sym(g_Wtl);
    __nv_bfloat16* Bth = (__nv_bfloat16*)sym(g_Bth);
    __nv_bfloat16* Btl = (__nv_bfloat16*)sym(g_Btl);
    float* Wfold  = (float*)sym(g_Wfold);

    // ---- CSR build (dst-grouped) ----
    int nb = (n + 1023) / 1024;
    cudaMemsetAsync(cnt, 0, (size_t)n * sizeof(int));
    k_hist<<<(E + 255) / 256, 256>>>(ei + E, cnt, E);
    k_scan1<<<nb, 1024>>>(cnt, rowptr, bsum, n);
    k_scan2<<<1, 64>>>(bsum, nb);
    k_scan3<<<(n + 255) / 256, 256>>>(rowptr, cursor, bsum, cnt, n);
    k_scatter<<<(E + n + 255) / 256, 256>>>(ei, cursor, col, E, n);

    int warpBlocks = (n + 7) / 8;
    int rowGrid = (n + 127) / 128;
    int tcGrid  = (n + 63) / 64;

    // ---- one-shot weight prep + x split ----
    k_prep<<<(47104 + 255) / 256, 256>>>(
        Ws[0], asv[0], adv[0], Ws[1], asv[1], adv[1],
        Ws[2], asv[2], adv[2], Ws[3], asv[3], adv[3],
        Ws[4], asv[4], adv[4], Bth, Btl, Wfold, Wth, Wtl);
    k_split<<<(n * 128 + 255) / 256, 256>>>(x, xh, xl, n * 128);

    // ---- layers 1..4 ----
    for (int L = 0; L < 4; L++) {
        int K = (L == 0) ? 128 : 64;
        k_gemm80_tc<<<tcGrid, 128>>>((L == 0) ? xh : ah, (L == 0) ? xl : al,
                                     Bth + L * 10240, Btl + L * 10240, hs, n, K);
        if (L < 3)
            k_agg_cat<<<warpBlocks, 256>>>(hs, rowptr, col, bs[L], ah, al,
                                           nullptr, nullptr, n);
        else
            k_agg_cat<<<warpBlocks, 256>>>(hs, rowptr, col, bs[L],
                                           nullptr, nullptr, acth, act, n);
    }

    // ---- layer 5 ----
    {
        dim3 g(1, rowGrid);
        k_gemm<1><<<g, 256>>>(act, Wfold, sbuf, n, 16, 64);
    }
    k_agg_mean<<<warpBlocks, 256>>>(acth, sbuf, rowptr, col, yh, yl, n);
    k_gemm_tc<<<tcGrid, 128>>>(yh, yl, Wth, Wtl, bs[4], (float*)d_out, n);
}

// round 10
// speedup vs baseline: 1.1750x; 1.1750x over previous
#include <cuda_runtime.h>
#include <cuda_bf16.h>
#include <cuda_fp16.h>
#include <cstddef>
#include <cstdint>

// Problem constants: N=50000, F=128, H=8, HID=8, CLS=40, E=1.6M
#define NMAX 50000
#define EMAX 1700000

// ---------------- static device scratch ----------------
// hs row = 64 floats (256B, line-aligned):
//   halves [0..63] = fp16 features (line 1), floats [32..39]=s_src, [40..47]=s_dst (line 2)
__device__ float g_hs   [(size_t)NMAX * 64];
__device__ float g_act  [(size_t)NMAX * 64];          // layer-4 activation fp32
__device__ __nv_bfloat16 g_xh[(size_t)NMAX * 128];
__device__ __nv_bfloat16 g_xl[(size_t)NMAX * 128];
__device__ __nv_bfloat16 g_ah[(size_t)NMAX * 64];
__device__ __nv_bfloat16 g_al[(size_t)NMAX * 64];
__device__ float g_sbuf [(size_t)NMAX * 16];
__device__ float g_ex   [(size_t)EMAX * 8];
__device__ int   g_col  [EMAX];
__device__ int   g_rowptr[NMAX + 1];
__device__ int   g_cursor[NMAX];
__device__ int   g_cnt   [NMAX];
__device__ int   g_bsum [64];
__device__ __nv_bfloat16 g_yh[(size_t)NMAX * 512];
__device__ __nv_bfloat16 g_yl[(size_t)NMAX * 512];
__device__ __nv_bfloat16 g_Wth[40 * 512];
__device__ __nv_bfloat16 g_Wtl[40 * 512];
__device__ __nv_bfloat16 g_Bth[4 * 80 * 128];
__device__ __nv_bfloat16 g_Btl[4 * 80 * 128];
__device__ float g_Wfold[64 * 16];

// ---------------- CSR build ----------------
__global__ void k_hist(const int* __restrict__ dst, int* cnt, int E) {
    int i = blockIdx.x * blockDim.x + threadIdx.x;
    if (i < E) atomicAdd(&cnt[dst[i]], 1);
}

__global__ void k_scan1(const int* __restrict__ cnt, int* rowptr, int* bsum, int n) {
    __shared__ int sm[1024];
    int tid = threadIdx.x;
    int i = blockIdx.x * 1024 + tid;
    int v = (i < n) ? cnt[i] + 1 : 0;          // +1 = self loop
    sm[tid] = v;
    __syncthreads();
    for (int off = 1; off < 1024; off <<= 1) {
        int t = (tid >= off) ? sm[tid - off] : 0;
        __syncthreads();
        sm[tid] += t;
        __syncthreads();
    }
    if (i < n) rowptr[i] = sm[tid] - v;
    if (tid == 1023) bsum[blockIdx.x] = sm[1023];
}

__global__ void k_scan2(int* bsum, int nb) {
    __shared__ int sm[64];
    int tid = threadIdx.x;
    sm[tid] = (tid < nb) ? bsum[tid] : 0;
    __syncthreads();
    if (tid == 0) {
        int run = 0;
        for (int j = 0; j < nb; j++) { int t = sm[j]; sm[j] = run; run += t; }
    }
    __syncthreads();
    if (tid < nb) bsum[tid] = sm[tid];
}

__global__ void k_scan3(int* rowptr, int* cursor, const int* __restrict__ bsum,
                        const int* __restrict__ cnt, int n) {
    int i = blockIdx.x * blockDim.x + threadIdx.x;
    if (i < n) {
        int v = rowptr[i] + bsum[i >> 10];
        rowptr[i] = v;
        cursor[i] = v;
        if (i == n - 1) rowptr[n] = v + cnt[i] + 1;
    }
}

__global__ void k_scatter(const int* __restrict__ ei, int* cursor, int* col, int E, int n) {
    int i = blockIdx.x * blockDim.x + threadIdx.x;
    if (i < E) {
        int s = ei[i];
        int d = ei[E + i];
        int p = atomicAdd(&cursor[d], 1);
        col[p] = s;
    } else if (i < E + n) {
        int nd = i - E;
        int p = atomicAdd(&cursor[nd], 1);
        col[p] = nd;
    }
}

// ---------------- split fp32 -> bf16 hi/lo planes ----------------
__global__ void k_split(const float* __restrict__ A, __nv_bfloat16* __restrict__ Ah,
                        __nv_bfloat16* __restrict__ Al, int sz)
{
    int i = blockIdx.x * blockDim.x + threadIdx.x;
    if (i < sz) {
        float v = A[i];
        __nv_bfloat16 hi = __float2bfloat16_rn(v);
        Ah[i] = hi;
        Al[i] = __float2bfloat16_rn(v - __bfloat162float(hi));
    }
}

// ---------------- fused weight prep ----------------
__global__ void k_prep(
    const float* __restrict__ W1, const float* __restrict__ as1, const float* __restrict__ ad1,
    const float* __restrict__ W2, const float* __restrict__ as2, const float* __restrict__ ad2,
    const float* __restrict__ W3, const float* __restrict__ as3, const float* __restrict__ ad3,
    const float* __restrict__ W4, const float* __restrict__ as4, const float* __restrict__ ad4,
    const float* __restrict__ W5, const float* __restrict__ as5, const float* __restrict__ ad5,
    __nv_bfloat16* __restrict__ Bth, __nv_bfloat16* __restrict__ Btl,
    float* __restrict__ Wfold,
    __nv_bfloat16* __restrict__ Wth, __nv_bfloat16* __restrict__ Wtl)
{
    int idx = blockIdx.x * blockDim.x + threadIdx.x;
    if (idx >= 47104) return;
    const float* Ws[4] = {W1, W2, W3, W4};
    const float* av[4] = {as1, as2, as3, as4};
    const float* dv[4] = {ad1, ad2, ad3, ad4};

    if (idx < 25600) {
        int L, K, t;
        if (idx < 10240) { L = 0; K = 128; t = idx; }
        else { int r = idx - 10240; L = 1 + r / 5120; K = 64; t = r % 5120; }
        int c = t / K;
        int k = t % K;
        const float* W = Ws[L];
        float val;
        if (c < 64) {
            val = W[(size_t)k * 64 + c];
        } else {
            int j = c - 64;
            int h = j & 7;
            const float* a = (j < 8) ? av[L] : dv[L];
            float sum = 0.f;
#pragma unroll
            for (int q = 0; q < 8; q++)
                sum += W[(size_t)k * 64 + h * 8 + q] * a[h * 8 + q];
            val = sum;
        }
        __nv_bfloat16 hi = __float2bfloat16_rn(val);
        Bth[L * 10240 + c * K + k] = hi;
        Btl[L * 10240 + c * K + k] = __float2bfloat16_rn(val - __bfloat162float(hi));
    } else if (idx < 26624) {
        int t = idx - 25600;
        int k = t >> 4;
        int j = t & 15;
        int h = j & 7;
        const float* a = (j < 8) ? as5 : ad5;
        float sum = 0.f;
        for (int c = 0; c < 40; c++)
            sum += W5[(size_t)k * 320 + h * 40 + c] * a[h * 40 + c];
        Wfold[t] = sum;
    } else {
        int t = idx - 26624;
        int c  = t / 512;
        int kk = t % 512;
        int h  = kk >> 6;
        int k  = kk & 63;
        float w = W5[(size_t)k * 320 + h * 40 + c];
        __nv_bfloat16 hi = __float2bfloat16_rn(w);
        Wth[t] = hi;
        Wtl[t] = __float2bfloat16_rn(w - __bfloat162float(hi));
    }
}

// ---------------- small fp32 SGEMM (layer-5 scores) ----------------
template<int TN>
__global__ __launch_bounds__(256) void k_gemm(
    const float* __restrict__ A, const float* __restrict__ B, float* __restrict__ C,
    int M, int Nc, int K)
{
    const int BN = 16 * TN;
    __shared__ float As[16][132];
    __shared__ float Bs[16][BN];
    int tid = threadIdx.x;
    int bm = blockIdx.y * 128;
    int bn = blockIdx.x * BN;
    int tx = tid & 15;
    int ty = tid >> 4;
    float acc[8][TN];
#pragma unroll
    for (int i = 0; i < 8; i++)
#pragma unroll
        for (int j = 0; j < TN; j++) acc[i][j] = 0.f;

    for (int k0 = 0; k0 < K; k0 += 16) {
#pragma unroll
        for (int it = 0; it < 2; it++) {
            int idx = tid + it * 256;
            int m  = idx >> 2;
            int kq = (idx & 3) * 4;
            int gm = bm + m;
            float4 v = make_float4(0.f, 0.f, 0.f, 0.f);
            if (gm < M) v = *(const float4*)(A + (size_t)gm * K + k0 + kq);
            As[kq + 0][m] = v.x;
            As[kq + 1][m] = v.y;
            As[kq + 2][m] = v.z;
            As[kq + 3][m] = v.w;
        }
        for (int idx = tid; idx < 16 * BN; idx += 256) {
            int kk = idx / BN;
            int cc = idx % BN;
            int gc = bn + cc;
            float v = 0.f;
            if (gc < Nc) v = B[(size_t)(k0 + kk) * Nc + gc];
            Bs[kk][cc] = v;
        }
        __syncthreads();
#pragma unroll
        for (int kk = 0; kk < 16; kk++) {
            float4 a0 = *(const float4*)(&As[kk][ty * 8]);
            float4 a1 = *(const float4*)(&As[kk][ty * 8 + 4]);
            float av[8] = {a0.x, a0.y, a0.z, a0.w, a1.x, a1.y, a1.z, a1.w};
            float bv[TN];
#pragma unroll
            for (int j = 0; j < TN; j++) bv[j] = Bs[kk][tx * TN + j];
#pragma unroll
            for (int i = 0; i < 8; i++)
#pragma unroll
                for (int j = 0; j < TN; j++) acc[i][j] += av[i] * bv[j];
        }
        __syncthreads();
    }
#pragma unroll
    for (int i = 0; i < 8; i++) {
        int gm = bm + ty * 8 + i;
        if (gm >= M) continue;
#pragma unroll
        for (int j = 0; j < TN; j++) {
            int gc = bn + tx * TN + j;
            if (gc < Nc) C[(size_t)gm * Nc + gc] = acc[i][j];
        }
    }
}

// ---------------- layers 1-4 fused GEMM on tensor cores -> hs ----------------
// Epilogue: features as fp16 into line 1, scores fp32 into line 2 (stride 64 fl).
__global__ __launch_bounds__(128) void k_gemm80_tc(
    const __nv_bfloat16* __restrict__ Ah, const __nv_bfloat16* __restrict__ Al,
    const __nv_bfloat16* __restrict__ Bth, const __nv_bfloat16* __restrict__ Btl,
    float* __restrict__ C, int n, int K)
{
    __shared__ __nv_bfloat16 sAh[64 * 72];
    __shared__ __nv_bfloat16 sAl[64 * 72];
    __shared__ __nv_bfloat16 sBh[80 * 72];
    __shared__ __nv_bfloat16 sBl[80 * 72];

    int tid  = threadIdx.x;
    int bm   = blockIdx.x * 64;
    int wid  = tid >> 5;
    int lane = tid & 31;
    int g    = lane >> 2;
    int t2   = (lane & 3) * 2;
    int mw   = wid * 16;
    int Ku   = K >> 1;

    float c0[10], c1[10], c2[10], c3[10];
#pragma unroll
    for (int j = 0; j < 10; j++) { c0[j] = c1[j] = c2[j] = c3[j] = 0.f; }

    const uint32_t* ah32 = (const uint32_t*)Ah;
    const uint32_t* al32 = (const uint32_t*)Al;
    const uint32_t* bh32 = (const uint32_t*)Bth;
    const uint32_t* bl32 = (const uint32_t*)Btl;

    for (int k0 = 0; k0 < K; k0 += 64) {
#pragma unroll
        for (int i = 0; i < 16; i++) {
            int idx = tid + i * 128;
            int row = idx >> 5;
            int cu  = idx & 31;
            int gr  = bm + row;
            uint32_t vh = 0, vl = 0;
            if (gr < n) {
                size_t off = (size_t)gr * Ku + (k0 >> 1) + cu;
                vh = ah32[off];
                vl = al32[off];
            }
            *(uint32_t*)(&sAh[row * 72 + cu * 2]) = vh;
            *(uint32_t*)(&sAl[row * 72 + cu * 2]) = vl;
        }
#pragma unroll
        for (int i = 0; i < 20; i++) {
            int idx = tid + i * 128;
            int c  = idx >> 5;
            int cu = idx & 31;
            size_t off = (size_t)c * Ku + (k0 >> 1) + cu;
            *(uint32_t*)(&sBh[c * 72 + cu * 2]) = bh32[off];
            *(uint32_t*)(&sBl[c * 72 + cu * 2]) = bl32[off];
        }
        __syncthreads();

#pragma unroll
        for (int ks = 0; ks < 64; ks += 16) {
            int arow0 = (mw + g) * 72 + ks + t2;
            int arow1 = (mw + g + 8) * 72 + ks + t2;
            uint32_t a0h = *(const uint32_t*)(&sAh[arow0]);
            uint32_t a1h = *(const uint32_t*)(&sAh[arow1]);
            uint32_t a2h = *(const uint32_t*)(&sAh[arow0 + 8]);
            uint32_t a3h = *(const uint32_t*)(&sAh[arow1 + 8]);
            uint32_t a0l = *(const uint32_t*)(&sAl[arow0]);
            uint32_t a1l = *(const uint32_t*)(&sAl[arow1]);
            uint32_t a2l = *(const uint32_t*)(&sAl[arow0 + 8]);
            uint32_t a3l = *(const uint32_t*)(&sAl[arow1 + 8]);
#pragma unroll
            for (int j = 0; j < 10; j++) {
                int brow = (j * 8 + g) * 72 + ks + t2;
                uint32_t b0h = *(const uint32_t*)(&sBh[brow]);
                uint32_t b1h = *(const uint32_t*)(&sBh[brow + 8]);
                uint32_t b0l = *(const uint32_t*)(&sBl[brow]);
                uint32_t b1l = *(const uint32_t*)(&sBl[brow + 8]);
                asm volatile(
                    "mma.sync.aligned.m16n8k16.row.col.f32.bf16.bf16.f32 "
                    "{%0,%1,%2,%3}, {%4,%5,%6,%7}, {%8,%9}, {%0,%1,%2,%3};"
                    : "+f"(c0[j]), "+f"(c1[j]), "+f"(c2[j]), "+f"(c3[j])
                    : "r"(a0h), "r"(a1h), "r"(a2h), "r"(a3h), "r"(b0h), "r"(b1h));
                asm volatile(
                    "mma.sync.aligned.m16n8k16.row.col.f32.bf16.bf16.f32 "
                    "{%0,%1,%2,%3}, {%4,%5,%6,%7}, {%8,%9}, {%0,%1,%2,%3};"
                    : "+f"(c0[j]), "+f"(c1[j]), "+f"(c2[j]), "+f"(c3[j])
                    : "r"(a0h), "r"(a1h), "r"(a2h), "r"(a3h), "r"(b0l), "r"(b1l));
                asm volatile(
                    "mma.sync.aligned.m16n8k16.row.col.f32.bf16.bf16.f32 "
                    "{%0,%1,%2,%3}, {%4,%5,%6,%7}, {%8,%9}, {%0,%1,%2,%3};"
                    : "+f"(c0[j]), "+f"(c1[j]), "+f"(c2[j]), "+f"(c3[j])
                    : "r"(a0l), "r"(a1l), "r"(a2l), "r"(a3l), "r"(b0h), "r"(b1h));
            }
        }
        __syncthreads();
    }

    int row0 = bm + mw + g;
    int row1 = row0 + 8;
#pragma unroll
    for (int j = 0; j < 10; j++) {
        if (j < 8) {
            if (row0 < n)
                *(__half2*)((__half*)(C + (size_t)row0 * 64) + j * 8 + t2) =
                    __float22half2_rn(make_float2(c0[j], c1[j]));
            if (row1 < n)
                *(__half2*)((__half*)(C + (size_t)row1 * 64) + j * 8 + t2) =
                    __float22half2_rn(make_float2(c2[j], c3[j]));
        } else {
            int fo = 32 + (j - 8) * 8 + t2;
            if (row0 < n)
                *(float2*)(C + (size_t)row0 * 64 + fo) = make_float2(c0[j], c1[j]);
            if (row1 < n)
                *(float2*)(C + (size_t)row1 * 64 + fo) = make_float2(c2[j], c3[j]);
        }
    }
}

// ---------------- concat-layer aggregation: aligned fp16 feature gather -------
__global__ __launch_bounds__(256) void k_agg_cat(
    const float* __restrict__ hs, const int* __restrict__ rowptr,
    const int* __restrict__ colx, const float* __restrict__ bias,
    __nv_bfloat16* __restrict__ oh, __nv_bfloat16* __restrict__ ol,
    float* __restrict__ outf, int n)
{
    int node = (blockIdx.x * blockDim.x + threadIdx.x) >> 5;
    if (node >= n) return;
    int lane = threadIdx.x & 31;
    int beg = rowptr[node], end = rowptr[node + 1];

    int sub = lane >> 4;
    int r   = lane & 15;
    int h   = r >> 1;
    int q   = r & 1;
    float sdv = __ldg(hs + (size_t)node * 64 + 40 + h);
    int hoff = h * 8 + q * 4;

    float4 acc = make_float4(0.f, 0.f, 0.f, 0.f);
    float d = 0.f;

    int e0 = beg;
    for (; e0 + 4 <= end; e0 += 4) {
        int siA = __ldg(colx + e0 + sub);
        int siB = __ldg(colx + e0 + 2 + sub);
        const float* rA = hs + (size_t)siA * 64;
        const float* rB = hs + (size_t)siB * 64;
        float sA = __ldg(rA + 32 + h);
        float sB = __ldg(rB + 32 + h);
        uint2 uA = __ldg((const uint2*)((const __half*)rA + hoff));
        uint2 uB = __ldg((const uint2*)((const __half*)rB + hoff));
        float2 fA0 = __half22float2(*(const __half2*)&uA.x);
        float2 fA1 = __half22float2(*(const __half2*)&uA.y);
        float2 fB0 = __half22float2(*(const __half2*)&uB.x);
        float2 fB1 = __half22float2(*(const __half2*)&uB.y);
        float aA = sA + sdv; aA = aA > 0.f ? aA : 0.2f * aA;
        float aB = sB + sdv; aB = aB > 0.f ? aB : 0.2f * aB;
        float eA = __expf(aA);
        float eB = __expf(aB);
        if (q == 0) d += eA + eB;
        acc.x += eA * fA0.x + eB * fB0.x;
        acc.y += eA * fA0.y + eB * fB0.y;
        acc.z += eA * fA1.x + eB * fB1.x;
        acc.w += eA * fA1.y + eB * fB1.y;
    }
    for (; e0 < end; e0 += 2) {
        int ee = e0 + sub;
        bool ok = ee < end;
        int si = ok ? __ldg(colx + ee) : node;
        const float* row = hs + (size_t)si * 64;
        float ssv = __ldg(row + 32 + h);
        uint2 u = __ldg((const uint2*)((const __half*)row + hoff));
        float2 f0 = __half22float2(*(const __half2*)&u.x);
        float2 f1 = __half22float2(*(const __half2*)&u.y);
        float al = ssv + sdv; al = al > 0.f ? al : 0.2f * al;
        float ex = ok ? __expf(al) : 0.f;
        if (q == 0) d += ex;
        acc.x += ex * f0.x;
        acc.y += ex * f0.y;
        acc.z += ex * f1.x;
        acc.w += ex * f1.y;
    }

    acc.x += __shfl_xor_sync(0xffffffffu, acc.x, 16);
    acc.y += __shfl_xor_sync(0xffffffffu, acc.y, 16);
    acc.z += __shfl_xor_sync(0xffffffffu, acc.z, 16);
    acc.w += __shfl_xor_sync(0xffffffffu, acc.w, 16);
    d     += __shfl_xor_sync(0xffffffffu, d, 16);
    d     += __shfl_xor_sync(0xffffffffu, d, 1);

    if (sub == 0) {
        float inv = 1.f / (d + 1e-16f);
        int ch = hoff;
        float4 b = __ldg((const float4*)(bias + ch));
        float4 rv;
        rv.x = acc.x * inv + b.x;
        rv.y = acc.y * inv + b.y;
        rv.z = acc.z * inv + b.z;
        rv.w = acc.w * inv + b.w;
        rv.x = rv.x > 0.f ? rv.x : 0.2f * rv.x;
        rv.y = rv.y > 0.f ? rv.y : 0.2f * rv.y;
        rv.z = rv.z > 0.f ? rv.z : 0.2f * rv.z;
        rv.w = rv.w > 0.f ? rv.w : 0.2f * rv.w;
        size_t o = (size_t)node * 64 + ch;
        if (oh) {
            __nv_bfloat16 h0 = __float2bfloat16_rn(rv.x);
            __nv_bfloat16 h1 = __float2bfloat16_rn(rv.y);
            __nv_bfloat16 h2 = __float2bfloat16_rn(rv.z);
            __nv_bfloat16 h3 = __float2bfloat16_rn(rv.w);
            *(__nv_bfloat162*)(oh + o)     = __nv_bfloat162(h0, h1);
            *(__nv_bfloat162*)(oh + o + 2) = __nv_bfloat162(h2, h3);
            __nv_bfloat162 lo01, lo23;
            lo01.x = __float2bfloat16_rn(rv.x - __bfloat162float(h0));
            lo01.y = __float2bfloat16_rn(rv.y - __bfloat162float(h1));
            lo23.x = __float2bfloat16_rn(rv.z - __bfloat162float(h2));
            lo23.y = __float2bfloat16_rn(rv.w - __bfloat162float(h3));
            *(__nv_bfloat162*)(ol + o)     = lo01;
            *(__nv_bfloat162*)(ol + o + 2) = lo23;
        } else {
            *(float4*)(outf + o) = rv;
        }
    }
}

// ---------------- layer-5 aggregation (R8-proven two-pass) ----------------
__global__ __launch_bounds__(256) void k_agg_mean(
    const float* __restrict__ xin, const float* __restrict__ s,
    const int* __restrict__ rowptr, const int* __restrict__ colx,
    __nv_bfloat16* __restrict__ yh, __nv_bfloat16* __restrict__ yl,
    float* __restrict__ exbuf, int n)
{
    int node = (blockIdx.x * blockDim.x + threadIdx.x) >> 5;
    if (node >= n) return;
    int lane = threadIdx.x & 31;
    int beg = rowptr[node], end = rowptr[node + 1];

    float sdv[8];
    const float* sd = s + (size_t)node * 16 + 8;
#pragma unroll
    for (int h = 0; h < 8; h++) sdv[h] = __ldg(sd + h);

    float dsum[8];
#pragma unroll
    for (int h = 0; h < 8; h++) dsum[h] = 0.f;

    for (int e = beg + lane; e < end; e += 32) {
        int si = colx[e];
        const float4* sp = (const float4*)(s + (size_t)si * 16);
        float4 s0 = __ldg(sp);
        float4 s1 = __ldg(sp + 1);
        float ss[8] = {s0.x, s0.y, s0.z, s0.w, s1.x, s1.y, s1.z, s1.w};
        float ex[8];
#pragma unroll
        for (int h = 0; h < 8; h++) {
            float al = ss[h] + sdv[h];
            al = al > 0.f ? al : 0.2f * al;
            ex[h] = __expf(al);
            dsum[h] += ex[h];
        }
        float4* ep = (float4*)(exbuf + (size_t)e * 8);
        ep[0] = make_float4(ex[0], ex[1], ex[2], ex[3]);
        ep[1] = make_float4(ex[4], ex[5], ex[6], ex[7]);
    }
#pragma unroll
    for (int off = 16; off; off >>= 1)
#pragma unroll
        for (int h = 0; h < 8; h++)
            dsum[h] += __shfl_xor_sync(0xffffffffu, dsum[h], off);

    float inv[8];
#pragma unroll
    for (int h = 0; h < 8; h++) inv[h] = 1.f / (dsum[h] + 1e-16f);
    __syncwarp();

    int sub = lane >> 4;
    int kb  = (lane & 15) * 4;

    float4 acc8[8];
#pragma unroll
    for (int h = 0; h < 8; h++) acc8[h] = make_float4(0.f, 0.f, 0.f, 0.f);

    int e0 = beg;
    for (; e0 + 2 <= end; e0 += 2) {
        int ee = e0 + sub;
        int si = __ldg(colx + ee);
        const float4* ap = (const float4*)(exbuf + (size_t)ee * 8);
        float4 q0 = __ldg(ap);
        float4 q1 = __ldg(ap + 1);
        float4 v  = __ldg((const float4*)(xin + (size_t)si * 64 + kb));
        float av[8] = {q0.x, q0.y, q0.z, q0.w, q1.x, q1.y, q1.z, q1.w};
#pragma unroll
        for (int h = 0; h < 8; h++) {
            acc8[h].x += av[h] * v.x;
            acc8[h].y += av[h] * v.y;
            acc8[h].z += av[h] * v.z;
            acc8[h].w += av[h] * v.w;
        }
    }
    if (e0 < end && sub == 0) {
        int si = __ldg(colx + e0);
        const float4* ap = (const float4*)(exbuf + (size_t)e0 * 8);
        float4 q0 = __ldg(ap);
        float4 q1 = __ldg(ap + 1);
        float4 v  = __ldg((const float4*)(xin + (size_t)si * 64 + kb));
        float av[8] = {q0.x, q0.y, q0.z, q0.w, q1.x, q1.y, q1.z, q1.w};
#pragma unroll
        for (int h = 0; h < 8; h++) {
            acc8[h].x += av[h] * v.x;
            acc8[h].y += av[h] * v.y;
            acc8[h].z += av[h] * v.z;
            acc8[h].w += av[h] * v.w;
        }
    }

#pragma unroll
    for (int h = 0; h < 8; h++) {
        acc8[h].x += __shfl_xor_sync(0xffffffffu, acc8[h].x, 16);
        acc8[h].y += __shfl_xor_sync(0xffffffffu, acc8[h].y, 16);
        acc8[h].z += __shfl_xor_sync(0xffffffffu, acc8[h].z, 16);
        acc8[h].w += __shfl_xor_sync(0xffffffffu, acc8[h].w, 16);
    }

    if (sub == 0) {
#pragma unroll
        for (int h = 0; h < 8; h++) {
            float w0 = acc8[h].x * inv[h];
            float w1 = acc8[h].y * inv[h];
            float w2 = acc8[h].z * inv[h];
            float w3 = acc8[h].w * inv[h];
            size_t o = (size_t)node * 512 + (size_t)h * 64 + kb;
            __nv_bfloat16 h0 = __float2bfloat16_rn(w0);
            __nv_bfloat16 h1 = __float2bfloat16_rn(w1);
            __nv_bfloat16 h2 = __float2bfloat16_rn(w2);
            __nv_bfloat16 h3 = __float2bfloat16_rn(w3);
            *(__nv_bfloat162*)(yh + o)     = __nv_bfloat162(h0, h1);
            *(__nv_bfloat162*)(yh + o + 2) = __nv_bfloat162(h2, h3);
            __nv_bfloat162 l01, l23;
            l01.x = __float2bfloat16_rn(w0 - __bfloat162float(h0));
            l01.y = __float2bfloat16_rn(w1 - __bfloat162float(h1));
            l23.x = __float2bfloat16_rn(w2 - __bfloat162float(h2));
            l23.y = __float2bfloat16_rn(w3 - __bfloat162float(h3));
            *(__nv_bfloat162*)(yl + o)     = l01;
            *(__nv_bfloat162*)(yl + o + 2) = l23;
        }
    }
}

// ---------------- final tensor-core GEMM + fused lsm ----------------
__global__ __launch_bounds__(128) void k_gemm_tc(
    const __nv_bfloat16* __restrict__ yh, const __nv_bfloat16* __restrict__ yl,
    const __nv_bfloat16* __restrict__ Wth, const __nv_bfloat16* __restrict__ Wtl,
    const float* __restrict__ b5, float* __restrict__ out, int n)
{
    __shared__ __nv_bfloat16 sAh[64 * 72];
    __shared__ __nv_bfloat16 sAl[64 * 72];
    __shared__ __nv_bfloat16 sBh[40 * 72];
    __shared__ __nv_bfloat16 sBl[40 * 72];

    int tid  = threadIdx.x;
    int bm   = blockIdx.x * 64;
    int wid  = tid >> 5;
    int lane = tid & 31;
    int g    = lane >> 2;
    int t2   = (lane & 3) * 2;
    int mw   = wid * 16;

    float c0[5], c1[5], c2[5], c3[5];
#pragma unroll
    for (int j = 0; j < 5; j++) { c0[j] = c1[j] = c2[j] = c3[j] = 0.f; }

    const uint32_t* yh32 = (const uint32_t*)yh;
    const uint32_t* yl32 = (const uint32_t*)yl;
    const uint32_t* wh32 = (const uint32_t*)Wth;
    const uint32_t* wl32 = (const uint32_t*)Wtl;

    for (int k0 = 0; k0 < 512; k0 += 64) {
#pragma unroll
        for (int i = 0; i < 16; i++) {
            int idx = tid + i * 128;
            int row = idx >> 5;
            int cu  = idx & 31;
            int gr  = bm + row;
            uint32_t vh = 0, vl = 0;
            if (gr < n) {
                size_t off = (size_t)gr * 256 + (k0 >> 1) + cu;
                vh = yh32[off];
                vl = yl32[off];
            }
            *(uint32_t*)(&sAh[row * 72 + cu * 2]) = vh;
            *(uint32_t*)(&sAl[row * 72 + cu * 2]) = vl;
        }
#pragma unroll
        for (int i = 0; i < 10; i++) {
            int idx = tid + i * 128;
            int c  = idx >> 5;
            int cu = idx & 31;
            size_t off = (size_t)c * 256 + (k0 >> 1) + cu;
            *(uint32_t*)(&sBh[c * 72 + cu * 2]) = wh32[off];
            *(uint32_t*)(&sBl[c * 72 + cu * 2]) = wl32[off];
        }
        __syncthreads();

#pragma unroll
        for (int ks = 0; ks < 64; ks += 16) {
            int arow0 = (mw + g) * 72 + ks + t2;
            int arow1 = (mw + g + 8) * 72 + ks + t2;
            uint32_t a0h = *(const uint32_t*)(&sAh[arow0]);
            uint32_t a1h = *(const uint32_t*)(&sAh[arow1]);
            uint32_t a2h = *(const uint32_t*)(&sAh[arow0 + 8]);
            uint32_t a3h = *(const uint32_t*)(&sAh[arow1 + 8]);
            uint32_t a0l = *(const uint32_t*)(&sAl[arow0]);
            uint32_t a1l = *(const uint32_t*)(&sAl[arow1]);
            uint32_t a2l = *(const uint32_t*)(&sAl[arow0 + 8]);
            uint32_t a3l = *(const uint32_t*)(&sAl[arow1 + 8]);
#pragma unroll
            for (int j = 0; j < 5; j++) {
                int brow = (j * 8 + g) * 72 + ks + t2;
                uint32_t b0h = *(const uint32_t*)(&sBh[brow]);
                uint32_t b1h = *(const uint32_t*)(&sBh[brow + 8]);
                uint32_t b0l = *(const uint32_t*)(&sBl[brow]);
                uint32_t b1l = *(const uint32_t*)(&sBl[brow + 8]);
                asm volatile(
                    "mma.sync.aligned.m16n8k16.row.col.f32.bf16.bf16.f32 "
                    "{%0,%1,%2,%3}, {%4,%5,%6,%7}, {%8,%9}, {%0,%1,%2,%3};"
                    : "+f"(c0[j]), "+f"(c1[j]), "+f"(c2[j]), "+f"(c3[j])
                    : "r"(a0h), "r"(a1h), "r"(a2h), "r"(a3h), "r"(b0h), "r"(b1h));
                asm volatile(
                    "mma.sync.aligned.m16n8k16.row.col.f32.bf16.bf16.f32 "
                    "{%0,%1,%2,%3}, {%4,%5,%6,%7}, {%8,%9}, {%0,%1,%2,%3};"
                    : "+f"(c0[j]), "+f"(c1[j]), "+f"(c2[j]), "+f"(c3[j])
                    : "r"(a0h), "r"(a1h), "r"(a2h), "r"(a3h), "r"(b0l), "r"(b1l));
                asm volatile(
                    "mma.sync.aligned.m16n8k16.row.col.f32.bf16.bf16.f32 "
                    "{%0,%1,%2,%3}, {%4,%5,%6,%7}, {%8,%9}, {%0,%1,%2,%3};"
                    : "+f"(c0[j]), "+f"(c1[j]), "+f"(c2[j]), "+f"(c3[j])
                    : "r"(a0l), "r"(a1l), "r"(a2l), "r"(a3l), "r"(b0h), "r"(b1h));
            }
        }
        __syncthreads();
    }

    int row0 = bm + mw + g;
    int row1 = row0 + 8;
    float v0[5], w0[5], v1[5], w1[5];
#pragma unroll
    for (int j = 0; j < 5; j++) {
        float2 b = *(const float2*)(b5 + j * 8 + t2);
        v0[j] = c0[j] * 0.125f + b.x;
        w0[j] = c1[j] * 0.125f + b.y;
        v1[j] = c2[j] * 0.125f + b.x;
        w1[j] = c3[j] * 0.125f + b.y;
    }
    float m0 = -1e30f, m1 = -1e30f;
#pragma unroll
    for (int j = 0; j < 5; j++) {
        m0 = fmaxf(m0, fmaxf(v0[j], w0[j]));
        m1 = fmaxf(m1, fmaxf(v1[j], w1[j]));
    }
    m0 = fmaxf(m0, __shfl_xor_sync(0xffffffffu, m0, 1));
    m0 = fmaxf(m0, __shfl_xor_sync(0xffffffffu, m0, 2));
    m1 = fmaxf(m1, __shfl_xor_sync(0xffffffffu, m1, 1));
    m1 = fmaxf(m1, __shfl_xor_sync(0xffffffffu, m1, 2));
    float s0 = 0.f, s1 = 0.f;
#pragma unroll
    for (int j = 0; j < 5; j++) {
        s0 += __expf(v0[j] - m0) + __expf(w0[j] - m0);
        s1 += __expf(v1[j] - m1) + __expf(w1[j] - m1);
    }
    s0 += __shfl_xor_sync(0xffffffffu, s0, 1);
    s0 += __shfl_xor_sync(0xffffffffu, s0, 2);
    s1 += __shfl_xor_sync(0xffffffffu, s1, 1);
    s1 += __shfl_xor_sync(0xffffffffu, s1, 2);
    float lse0 = m0 + __logf(s0);
    float lse1 = m1 + __logf(s1);

    if (row0 < n) {
#pragma unroll
        for (int j = 0; j < 5; j++)
            *(float2*)(out + (size_t)row0 * 40 + j * 8 + t2) =
                make_float2(v0[j] - lse0, w0[j] - lse0);
    }
    if (row1 < n) {
#pragma unroll
        for (int j = 0; j < 5; j++)
            *(float2*)(out + (size_t)row1 * 40 + j * 8 + t2) =
                make_float2(v1[j] - lse1, w1[j] - lse1);
    }
}

// ---------------- host ----------------
static void* sym(const void* s) {
    void* p = nullptr;
    cudaGetSymbolAddress(&p, s);
    return p;
}

extern "C" void kernel_launch(void* const* d_in, const int* in_sizes, int n_in,
                              void* d_out, int out_size)
{
    const float* x   = (const float*)d_in[0];
    const int*   ei  = (const int*)d_in[1];
    const float* Ws[5]  = {(const float*)d_in[2],  (const float*)d_in[6],
                           (const float*)d_in[10], (const float*)d_in[14],
                           (const float*)d_in[18]};
    const float* asv[5] = {(const float*)d_in[3],  (const float*)d_in[7],
                           (const float*)d_in[11], (const float*)d_in[15],
                           (const float*)d_in[19]};
    const float* adv[5] = {(const float*)d_in[4],  (const float*)d_in[8],
                           (const float*)d_in[12], (const float*)d_in[16],
                           (const float*)d_in[20]};
    const float* bs[5]  = {(const float*)d_in[5],  (const float*)d_in[9],
                           (const float*)d_in[13], (const float*)d_in[17],
                           (const float*)d_in[21]};

    int n = in_sizes[0] / 128;
    int E = in_sizes[1] / 2;

    float* hs     = (float*)sym(g_hs);
    float* act    = (float*)sym(g_act);
    float* sbuf   = (float*)sym(g_sbuf);
    float* exbuf  = (float*)sym(g_ex);
    int*   col    = (int*)  sym(g_col);
    int*   rowptr = (int*)  sym(g_rowptr);
    int*   cursor = (int*)  sym(g_cursor);
    int*   cnt    = (int*)  sym(g_cnt);
    int*   bsum   = (int*)  sym(g_bsum);
    __nv_bfloat16* xh  = (__nv_bfloat16*)sym(g_xh);
    __nv_bfloat16* xl  = (__nv_bfloat16*)sym(g_xl);
    __nv_bfloat16* ah  = (__nv_bfloat16*)sym(g_ah);
    __nv_bfloat16* al  = (__nv_bfloat16*)sym(g_al);
    __nv_bfloat16* yh  = (__nv_bfloat16*)sym(g_yh);
    __nv_bfloat16* yl  = (__nv_bfloat16*)sym(g_yl);
    __nv_bfloat16* Wth = (__nv_bfloat16*)sym(g_Wth);
    __nv_bfloat16* Wtl = (__nv_bfloat16*)sym(g_Wtl);
    __nv_bfloat16* Bth = (__nv_bfloat16*)sym(g_Bth);
    __nv_bfloat16* Btl = (__nv_bfloat16*)sym(g_Btl);
    float* Wfold  = (float*)sym(g_Wfold);

    // ---- CSR build (dst-grouped) ----
    int nb = (n + 1023) / 1024;
    cudaMemsetAsync(cnt, 0, (size_t)n * sizeof(int));
    k_hist<<<(E + 255) / 256, 256>>>(ei + E, cnt, E);
    k_scan1<<<nb, 1024>>>(cnt, rowptr, bsum, n);
    k_scan2<<<1, 64>>>(bsum, nb);
    k_scan3<<<(n + 255) / 256, 256>>>(rowptr, cursor, bsum, cnt, n);
    k_scatter<<<(E + n + 255) / 256, 256>>>(ei, cursor, col, E, n);

    int warpBlocks = (n + 7) / 8;
    int rowGrid = (n + 127) / 128;
    int tcGrid  = (n + 63) / 64;

    // ---- one-shot weight prep + x split ----
    k_prep<<<(47104 + 255) / 256, 256>>>(
        Ws[0], asv[0], adv[0], Ws[1], asv[1], adv[1],
        Ws[2], asv[2], adv[2], Ws[3], asv[3], adv[3],
        Ws[4], asv[4], adv[4], Bth, Btl, Wfold, Wth, Wtl);
    k_split<<<(n * 128 + 255) / 256, 256>>>(x, xh, xl, n * 128);

    // ---- layers 1..4 ----
    for (int L = 0; L < 4; L++) {
        int K = (L == 0) ? 128 : 64;
        k_gemm80_tc<<<tcGrid, 128>>>((L == 0) ? xh : ah, (L == 0) ? xl : al,
                                     Bth + L * 10240, Btl + L * 10240, hs, n, K);
        if (L < 3)
            k_agg_cat<<<warpBlocks, 256>>>(hs, rowptr, col, bs[L], ah, al,
                                           nullptr, n);
        else
            k_agg_cat<<<warpBlocks, 256>>>(hs, rowptr, col, bs[L],
                                           nullptr, nullptr, act, n);
    }

    // ---- layer 5 ----
    {
        dim3 g(1, rowGrid);
        k_gemm<1><<<g, 256>>>(act, Wfold, sbuf, n, 16, 64);
    }
    k_agg_mean<<<warpBlocks, 256>>>(act, sbuf, rowptr, col, yh, yl, exbuf, n);
    k_gemm_tc<<<tcGrid, 128>>>(yh, yl, Wth, Wtl, bs[4], (float*)d_out, n);

    // layer-4 activation also needs bf16 planes for... (not needed: layer 5 GEMMs
    // consume act in fp32 and yh/yl; no further use of ah/al after layer 4)
}